// round 1
// baseline (speedup 1.0000x reference)
#include <cuda_runtime.h>

// Problem constants
#define NB     4
#define NSEQ   1024
#define NHEADS 12
#define NDH    64
#define NINNER 768   // 12*64
// combined score scale = 0.5 / sqrt(768)
#define SCORE_SCALE 0.018042195912175807f

// Scratch (static device memory: allowed; cudaMalloc is not)
__device__ __align__(16) float g_qkv [NB * NSEQ * 3 * NINNER]; // [b*n][3*768]
__device__ __align__(16) float g_pos2[NB * NSEQ * 2 * NINNER]; // [b*n][2*768]
__device__ __align__(16) float g_ao  [NB * NSEQ * NINNER];     // [b*n][768]

// ---------------------------------------------------------------------------
// Generic fp32 SGEMM: C[M,N] = A[M,K] @ B[K,N] (+ bias[N])
// Block tile 128x64, BK=16, 256 threads, 8x4 per-thread fragment.
// Assumes M%128==0, N%64==0, K%16==0 (true for all three calls).
// ---------------------------------------------------------------------------
__global__ void __launch_bounds__(256) sgemm_kernel(
    const float* __restrict__ A, const float* __restrict__ Bm,
    const float* __restrict__ bias, float* __restrict__ C,
    int M, int Nn, int K, int hasBias)
{
    __shared__ float As[128][17];  // padded: broadcast reads, low-conflict writes
    __shared__ float Bs[16][64];

    const int tid = threadIdx.x;
    const int tx = tid & 15, ty = tid >> 4;
    const int bm = blockIdx.y << 7, bn = blockIdx.x << 6;

    float acc[8][4];
#pragma unroll
    for (int r = 0; r < 8; r++)
#pragma unroll
        for (int c = 0; c < 4; c++) acc[r][c] = 0.f;

    for (int k0 = 0; k0 < K; k0 += 16) {
        // A tile 128x16: coalesced float4 reads, scalar smem writes
#pragma unroll
        for (int i = 0; i < 2; i++) {
            int lin = tid + (i << 8);
            int m = lin >> 2, kv = (lin & 3) << 2;
            const float4 a4 = *(const float4*)(A + (size_t)(bm + m) * K + k0 + kv);
            As[m][kv + 0] = a4.x; As[m][kv + 1] = a4.y;
            As[m][kv + 2] = a4.z; As[m][kv + 3] = a4.w;
        }
        // B tile 16x64: fully coalesced, conflict-free
        {
            int kk = tid >> 4, nv = (tid & 15) << 2;
            *(float4*)&Bs[kk][nv] =
                *(const float4*)(Bm + (size_t)(k0 + kk) * Nn + bn + nv);
        }
        __syncthreads();
#pragma unroll
        for (int k = 0; k < 16; k++) {
            const float4 b4 = *(const float4*)&Bs[k][tx << 2];
#pragma unroll
            for (int r = 0; r < 8; r++) {
                const float a = As[(ty << 3) + r][k];
                acc[r][0] += a * b4.x;
                acc[r][1] += a * b4.y;
                acc[r][2] += a * b4.z;
                acc[r][3] += a * b4.w;
            }
        }
        __syncthreads();
    }

#pragma unroll
    for (int r = 0; r < 8; r++) {
        float4 v = make_float4(acc[r][0], acc[r][1], acc[r][2], acc[r][3]);
        if (hasBias) {
            const float4 bb = *(const float4*)(bias + bn + (tx << 2));
            v.x += bb.x; v.y += bb.y; v.z += bb.z; v.w += bb.w;
        }
        *(float4*)(C + (size_t)(bm + (ty << 3) + r) * Nn + bn + (tx << 2)) = v;
    }
}

// ---------------------------------------------------------------------------
// Fused dual-score flash attention.
// Grid: (16 q-tiles, 48 b*h). Block: 256 threads (16x16 logical).
// Each block: 64 query rows of one (b,h); loops over 16 K-tiles of 64 rows.
// scores = (q.k + q_pos.k_pos) * 0.5/sqrt(768), online softmax, o += P@V.
// Dynamic smem 96KB: sQ,sQp [row][d]; sK,sKp transposed [d][col]; sV [row][d]; sP.
// ---------------------------------------------------------------------------
__global__ void __launch_bounds__(256) attn_kernel()
{
    extern __shared__ float sm[];
    float* sQ  = sm;
    float* sQp = sm + 4096;
    float* sK  = sm + 8192;
    float* sKp = sm + 12288;
    float* sV  = sm + 16384;
    float* sP  = sm + 20480;

    const int tid = threadIdx.x;
    const int tx = tid & 15, ty = tid >> 4;
    const int bh = blockIdx.y;
    const int b = bh / NHEADS, h = bh % NHEADS;
    const int qbase = blockIdx.x << 6;

    const float* qptr  = g_qkv  + (size_t)((b << 10) + qbase) * 2304 + h * 64;
    const float* qpptr = g_pos2 + (size_t)((b << 10) + qbase) * 1536 + h * 64;

    // Load Q / Q_pos tiles (64x64), coalesced float4
#pragma unroll
    for (int i = 0; i < 4; i++) {
        int lin = tid + (i << 8);
        int row = lin >> 4, f4 = (lin & 15) << 2;
        *(float4*)&sQ [row * 64 + f4] = *(const float4*)(qptr  + (size_t)row * 2304 + f4);
        *(float4*)&sQp[row * 64 + f4] = *(const float4*)(qpptr + (size_t)row * 1536 + f4);
    }

    float o[4][4];
    float mrow[4], lrow[4];
#pragma unroll
    for (int r = 0; r < 4; r++) {
        mrow[r] = -1e30f; lrow[r] = 0.f;
#pragma unroll
        for (int c = 0; c < 4; c++) o[r][c] = 0.f;
    }

    for (int kt = 0; kt < 16; kt++) {
        const int kbase = kt << 6;
        const float* kptr  = g_qkv  + (size_t)((b << 10) + kbase) * 2304 + 768  + h * 64;
        const float* kpptr = g_pos2 + (size_t)((b << 10) + kbase) * 1536 + 768  + h * 64;
        const float* vptr  = g_qkv  + (size_t)((b << 10) + kbase) * 2304 + 1536 + h * 64;

        __syncthreads();  // previous tile's PV done before overwriting smem
#pragma unroll
        for (int i = 0; i < 4; i++) {
            int lin = tid + (i << 8);
            // K, K_pos: store transposed [d][j]; smem writes conflict-free (j contiguous)
            int j = lin & 63, dv = (lin >> 6) << 2;
            float4 k4 = *(const float4*)(kptr + (size_t)j * 2304 + dv);
            sK[(dv + 0) * 64 + j] = k4.x;
            sK[(dv + 1) * 64 + j] = k4.y;
            sK[(dv + 2) * 64 + j] = k4.z;
            sK[(dv + 3) * 64 + j] = k4.w;
            float4 kp4 = *(const float4*)(kpptr + (size_t)j * 1536 + dv);
            sKp[(dv + 0) * 64 + j] = kp4.x;
            sKp[(dv + 1) * 64 + j] = kp4.y;
            sKp[(dv + 2) * 64 + j] = kp4.z;
            sKp[(dv + 3) * 64 + j] = kp4.w;
            // V row-major, coalesced
            int row = lin >> 4, f4 = (lin & 15) << 2;
            *(float4*)&sV[row * 64 + f4] = *(const float4*)(vptr + (size_t)row * 2304 + f4);
        }
        __syncthreads();

        // S = Q.K^T + Qp.Kp^T  (4x4 fragment per thread)
        float acc[4][4];
#pragma unroll
        for (int r = 0; r < 4; r++)
#pragma unroll
            for (int c = 0; c < 4; c++) acc[r][c] = 0.f;

#pragma unroll 16
        for (int d = 0; d < 64; d++) {
            const float4 k4  = *(const float4*)&sK [d * 64 + (tx << 2)];
            const float4 kp4 = *(const float4*)&sKp[d * 64 + (tx << 2)];
#pragma unroll
            for (int r = 0; r < 4; r++) {
                const float q  = sQ [((ty << 2) + r) * 64 + d];
                const float qp = sQp[((ty << 2) + r) * 64 + d];
                acc[r][0] += q * k4.x + qp * kp4.x;
                acc[r][1] += q * k4.y + qp * kp4.y;
                acc[r][2] += q * k4.z + qp * kp4.z;
                acc[r][3] += q * k4.w + qp * kp4.w;
            }
        }

        // Online softmax (rows split across ty; reduce across 16 tx lanes)
#pragma unroll
        for (int r = 0; r < 4; r++) {
            const float s0 = acc[r][0] * SCORE_SCALE;
            const float s1 = acc[r][1] * SCORE_SCALE;
            const float s2 = acc[r][2] * SCORE_SCALE;
            const float s3 = acc[r][3] * SCORE_SCALE;
            float mx = fmaxf(fmaxf(s0, s1), fmaxf(s2, s3));
#pragma unroll
            for (int off = 8; off > 0; off >>= 1)
                mx = fmaxf(mx, __shfl_xor_sync(0xffffffffu, mx, off, 16));
            const float mnew  = fmaxf(mrow[r], mx);
            const float alpha = __expf(mrow[r] - mnew);
            const float p0 = __expf(s0 - mnew);
            const float p1 = __expf(s1 - mnew);
            const float p2 = __expf(s2 - mnew);
            const float p3 = __expf(s3 - mnew);
            float rs = p0 + p1 + p2 + p3;
#pragma unroll
            for (int off = 8; off > 0; off >>= 1)
                rs += __shfl_xor_sync(0xffffffffu, rs, off, 16);
            lrow[r] = lrow[r] * alpha + rs;
            mrow[r] = mnew;
            o[r][0] *= alpha; o[r][1] *= alpha; o[r][2] *= alpha; o[r][3] *= alpha;
            *(float4*)&sP[((ty << 2) + r) * 64 + (tx << 2)] = make_float4(p0, p1, p2, p3);
        }
        __syncthreads();

        // O += P @ V
#pragma unroll 8
        for (int j = 0; j < 64; j++) {
            const float4 v4 = *(const float4*)&sV[j * 64 + (tx << 2)];
#pragma unroll
            for (int r = 0; r < 4; r++) {
                const float p = sP[((ty << 2) + r) * 64 + j];
                o[r][0] += p * v4.x;
                o[r][1] += p * v4.y;
                o[r][2] += p * v4.z;
                o[r][3] += p * v4.w;
            }
        }
    }

    // Epilogue: normalize, write [b, n, h*64+d] layout
#pragma unroll
    for (int r = 0; r < 4; r++) {
        const float inv = 1.f / lrow[r];
        const float4 v = make_float4(o[r][0] * inv, o[r][1] * inv,
                                     o[r][2] * inv, o[r][3] * inv);
        const int row_g = (b << 10) + qbase + (ty << 2) + r;
        *(float4*)(g_ao + (size_t)row_g * 768 + h * 64 + (tx << 2)) = v;
    }
}

// ---------------------------------------------------------------------------
extern "C" void kernel_launch(void* const* d_in, const int* in_sizes, int n_in,
                              void* d_out, int out_size)
{
    (void)in_sizes; (void)n_in; (void)out_size;
    const float* x     = (const float*)d_in[0];
    const float* pos   = (const float*)d_in[1];
    const float* w_qkv = (const float*)d_in[2];
    const float* w_qkp = (const float*)d_in[3];
    const float* w_out = (const float*)d_in[4];
    const float* b_out = (const float*)d_in[5];
    float* out = (float*)d_out;

    void *p_qkv, *p_pos, *p_ao;
    cudaGetSymbolAddress(&p_qkv, g_qkv);
    cudaGetSymbolAddress(&p_pos, g_pos2);
    cudaGetSymbolAddress(&p_ao,  g_ao);

    cudaFuncSetAttribute(attn_kernel,
                         cudaFuncAttributeMaxDynamicSharedMemorySize, 98304);

    dim3 blk(256);
    // qkv = x @ w_qkv                [4096 x 2304]
    sgemm_kernel<<<dim3(2304 / 64, 4096 / 128), blk>>>(
        x, w_qkv, nullptr, (float*)p_qkv, 4096, 2304, 768, 0);
    // qk_pos = pos @ w_qk_pos        [4096 x 1536]
    sgemm_kernel<<<dim3(1536 / 64, 4096 / 128), blk>>>(
        pos, w_qkp, nullptr, (float*)p_pos, 4096, 1536, 768, 0);
    // fused dual-score attention -> g_ao
    attn_kernel<<<dim3(16, 48), blk, 98304>>>();
    // out = ao @ w_out + b_out       [4096 x 768]
    sgemm_kernel<<<dim3(768 / 64, 4096 / 128), blk>>>(
        (const float*)p_ao, w_out, b_out, out, 4096, 768, 768, 1);
}

// round 2
// speedup vs baseline: 1.2876x; 1.2876x over previous
#include <cuda_runtime.h>
#include <stdint.h>

// Problem constants
#define NB     4
#define NSEQ   1024
#define NHEADS 12
#define NINNER 768   // 12*64
// combined score scale = 0.5 / sqrt(768)
#define SCORE_SCALE 0.018042195912175807f

// Scratch (static device memory: allowed; cudaMalloc is not)
__device__ __align__(16) float g_qkv [NB * NSEQ * 3 * NINNER]; // [b*n][3*768]
__device__ __align__(16) float g_pos2[NB * NSEQ * 2 * NINNER]; // [b*n][2*768]
__device__ __align__(16) float g_ao  [NB * NSEQ * NINNER];     // [b*n][768]

// ---------------------------------------------------------------------------
// tf32 helpers
// ---------------------------------------------------------------------------
__device__ __forceinline__ uint32_t f2tf(float x) {
    uint32_t u;
    asm("cvt.rna.tf32.f32 %0, %1;" : "=r"(u) : "f"(x));
    return u;
}

// D += A@B, m16n8k8, A row-major, B col-major, tf32 in / f32 acc
__device__ __forceinline__ void mma8(float* d, const uint32_t* a, const uint32_t* b) {
    asm volatile(
        "mma.sync.aligned.m16n8k8.row.col.f32.tf32.tf32.f32 "
        "{%0,%1,%2,%3}, {%4,%5,%6,%7}, {%8,%9}, {%0,%1,%2,%3};\n"
        : "+f"(d[0]), "+f"(d[1]), "+f"(d[2]), "+f"(d[3])
        : "r"(a[0]), "r"(a[1]), "r"(a[2]), "r"(a[3]), "r"(b[0]), "r"(b[1]));
}

// ---------------------------------------------------------------------------
// Tensor-core SGEMM (tf32): C[M,N] = A[M,K] @ B[K,N] (+ bias)
// Block: 128 threads (4 warps, 2x2), tile 128x128, BK=16.
// Smem holds operands already permuted into mma fragment layout:
//   A-frag slot for (row,col):  lane=(row&7)*4+(col&3), slot=((row>>3)&1)|((col&4)?2:0)
//   B-frag slot for (k,n):      lane=(n&7)*4+(k&3),     slot=(k>>2)&1
// Mainloop per warp per k8-step: 4 LDS.128 (A) + 8 LDS.64 (B) -> 32 MMA.
// Requires M%128==0, N%128==0, K%16==0 (true for all three calls).
// ---------------------------------------------------------------------------
__global__ void __launch_bounds__(128) sgemm_tc(
    const float* __restrict__ A, const float* __restrict__ Bm,
    const float* __restrict__ bias, float* __restrict__ C,
    int M, int Nn, int K, int hasBias)
{
    __shared__ uint32_t As[2 * 8 * 32 * 4];   // [kstep][mtile][lane][slot]
    __shared__ uint32_t Bs[2 * 16 * 32 * 2];  // [kstep][ntile][lane][slot]

    const int tid  = threadIdx.x;
    const int lane = tid & 31, warp = tid >> 5;
    const int wm = warp >> 1, wn = warp & 1;
    const int g = lane >> 2, t = lane & 3;
    const int bm = blockIdx.y << 7, bn = blockIdx.x << 7;

    float acc[4][8][4];
#pragma unroll
    for (int mt = 0; mt < 4; mt++)
#pragma unroll
        for (int nt = 0; nt < 8; nt++)
#pragma unroll
            for (int i = 0; i < 4; i++) acc[mt][nt][i] = 0.f;

    for (int k0 = 0; k0 < K; k0 += 16) {
        // ---- stage A tile (128x16) into fragment layout ----
#pragma unroll
        for (int i = 0; i < 4; i++) {
            int lin = tid + (i << 7);          // 0..511
            int row = lin >> 2;                // 0..127
            int kc  = (lin & 3) << 2;          // 0,4,8,12
            float4 v = *(const float4*)(A + (size_t)(bm + row) * K + k0 + kc);
            int kstep = kc >> 3;
            int mt    = row >> 4;
            int base  = ((kstep << 3) + mt) * 32 + ((row & 7) << 2);
            int slot  = ((row >> 3) & 1) | ((kc & 4) ? 2 : 0);
            As[(base + 0) * 4 + slot] = f2tf(v.x);
            As[(base + 1) * 4 + slot] = f2tf(v.y);
            As[(base + 2) * 4 + slot] = f2tf(v.z);
            As[(base + 3) * 4 + slot] = f2tf(v.w);
        }
        // ---- stage B tile (16x128) into fragment layout ----
#pragma unroll
        for (int i = 0; i < 4; i++) {
            int lin = tid + (i << 7);          // 0..511
            int row = lin >> 5;                // k: 0..15
            int c4  = (lin & 31) << 2;         // n: 0..124
            float4 v = *(const float4*)(Bm + (size_t)(k0 + row) * Nn + bn + c4);
            int kstep = row >> 3;
            int slot  = (row >> 2) & 1;
            int nt    = c4 >> 3;               // constant across the 4 (c4&7 in {0,4})
            int lbase = ((c4 & 7) << 2) + (row & 3);
            int base  = ((kstep << 4) + nt) * 32;
            Bs[(base + lbase + 0) * 2 + slot] = f2tf(v.x);
            Bs[(base + lbase + 4) * 2 + slot] = f2tf(v.y);
            Bs[(base + lbase + 8) * 2 + slot] = f2tf(v.z);
            Bs[(base + lbase + 12) * 2 + slot] = f2tf(v.w);
        }
        __syncthreads();

        // ---- mainloop: 2 k8-steps ----
#pragma unroll
        for (int ks = 0; ks < 2; ks++) {
            uint32_t bf[8][2];
#pragma unroll
            for (int nt = 0; nt < 8; nt++) {
                int ntg = (wn << 3) + nt;
                uint2 bb = *(const uint2*)&Bs[(((ks << 4) + ntg) * 32 + lane) * 2];
                bf[nt][0] = bb.x; bf[nt][1] = bb.y;
            }
#pragma unroll
            for (int mt = 0; mt < 4; mt++) {
                int mtg = (wm << 2) + mt;
                uint4 aa = *(const uint4*)&As[(((ks << 3) + mtg) * 32 + lane) * 4];
                uint32_t af[4] = {aa.x, aa.y, aa.z, aa.w};
#pragma unroll
                for (int nt = 0; nt < 8; nt++) mma8(acc[mt][nt], af, bf[nt]);
            }
        }
        __syncthreads();
    }

    // ---- epilogue ----
#pragma unroll
    for (int mt = 0; mt < 4; mt++) {
#pragma unroll
        for (int nt = 0; nt < 8; nt++) {
            int row0 = bm + (wm << 6) + (mt << 4) + g;
            int col0 = bn + (wn << 6) + (nt << 3) + (t << 1);
            float b0 = 0.f, b1 = 0.f;
            if (hasBias) {
                float2 bb = *(const float2*)(bias + col0);
                b0 = bb.x; b1 = bb.y;
            }
            float2 v0 = make_float2(acc[mt][nt][0] + b0, acc[mt][nt][1] + b1);
            float2 v1 = make_float2(acc[mt][nt][2] + b0, acc[mt][nt][3] + b1);
            *(float2*)(C + (size_t)row0 * Nn + col0) = v0;
            *(float2*)(C + (size_t)(row0 + 8) * Nn + col0) = v1;
        }
    }
}

// ---------------------------------------------------------------------------
// Fused dual-score flash attention, tensor-core version.
// Grid: (16 q-tiles, 48 b*h). Block: 128 threads = 4 warps.
// Each warp owns 16 q-rows (one m16 stripe of the 64-row q-tile); Q and Q_pos
// fragments live in registers for the whole kv loop. Per 64-row kv tile:
//   S = Q@K^T + Qp@Kp^T (128 mma/warp), online softmax, P -> per-warp smem
//   (A-fragment layout, warp-private so only __syncwarp), O += P@V (64 mma).
// Dynamic smem 64KB: sK, sKp, sV (B-frag layout, 16KB each) + sP (16KB).
// ---------------------------------------------------------------------------
__global__ void __launch_bounds__(128) attn_tc()
{
    extern __shared__ uint32_t sm[];
    uint32_t* sK  = sm;            // [kstep(d)][ntile(j)][lane][2]
    uint32_t* sKp = sm + 4096;
    uint32_t* sV  = sm + 8192;     // [kstep(j)][ntile(d)][lane][2]
    uint32_t* sP  = sm + 12288;    // per-warp: [kstep(j)][lane][4]

    const int tid  = threadIdx.x;
    const int lane = tid & 31, w = tid >> 5;
    const int g = lane >> 2, t = lane & 3;
    const int bh = blockIdx.y;
    const int b = bh / NHEADS, h = bh % NHEADS;
    const int qbase = blockIdx.x << 6;
    const int hoff = h << 6;

    // ---- preload Q / Qpos fragments (16 rows per warp, full d=64) ----
    uint32_t qa[8][4], qpa[8][4];
    {
        const int r0 = (b << 10) + qbase + (w << 4);
#pragma unroll
        for (int ks = 0; ks < 8; ks++) {
#pragma unroll
            for (int s = 0; s < 4; s++) {
                int row = r0 + g + ((s & 1) << 3);
                int col = (ks << 3) + t + ((s & 2) << 1);
                qa[ks][s]  = f2tf(g_qkv [(size_t)row * 2304 + hoff + col]);
                qpa[ks][s] = f2tf(g_pos2[(size_t)row * 1536 + hoff + col]);
            }
        }
    }

    float o[8][4];
#pragma unroll
    for (int nt = 0; nt < 8; nt++)
#pragma unroll
        for (int i = 0; i < 4; i++) o[nt][i] = 0.f;
    float m0 = -1e30f, m1 = -1e30f, l0 = 0.f, l1 = 0.f;

    for (int kt = 0; kt < 16; kt++) {
        const int kbase = kt << 6;
        const size_t krow = (size_t)((b << 10) + kbase);

        __syncthreads();   // previous tile's reads complete before restage
        // ---- stage K, Kp, V (64x64 each) into fragment layouts ----
#pragma unroll
        for (int i = 0; i < 8; i++) {
            int lin = tid + (i << 7);      // 0..1023
            int j  = lin >> 4;             // kv row 0..63
            int c4 = (lin & 15) << 2;      // d 0,4,..,60
            float4 kv = *(const float4*)(g_qkv  + (krow + j) * 2304 + 768  + hoff + c4);
            float4 kp = *(const float4*)(g_pos2 + (krow + j) * 1536 + 768  + hoff + c4);
            float4 vv = *(const float4*)(g_qkv  + (krow + j) * 2304 + 1536 + hoff + c4);
#pragma unroll
            for (int jj = 0; jj < 4; jj++) {
                int d = c4 + jj;
                float kx = (jj == 0) ? kv.x : (jj == 1) ? kv.y : (jj == 2) ? kv.z : kv.w;
                float px = (jj == 0) ? kp.x : (jj == 1) ? kp.y : (jj == 2) ? kp.z : kp.w;
                float vx = (jj == 0) ? vv.x : (jj == 1) ? vv.y : (jj == 2) ? vv.z : vv.w;
                // K/Kp: B-frag for S (k=d, n=j)
                int ia = ((((d >> 3) << 3) + (j >> 3)) * 32 + ((j & 7) << 2) + (d & 3)) * 2
                         + ((d >> 2) & 1);
                sK[ia]  = f2tf(kx);
                sKp[ia] = f2tf(px);
                // V: B-frag for PV (k=j, n=d)
                int iv = ((((j >> 3) << 3) + (d >> 3)) * 32 + ((d & 7) << 2) + (j & 3)) * 2
                         + ((j >> 2) & 1);
                sV[iv] = f2tf(vx);
            }
        }
        __syncthreads();

        // ---- S = Q@K^T + Qp@Kp^T ----
        float s[8][4];
#pragma unroll
        for (int nt = 0; nt < 8; nt++)
#pragma unroll
            for (int i = 0; i < 4; i++) s[nt][i] = 0.f;
#pragma unroll
        for (int ks = 0; ks < 8; ks++) {
#pragma unroll
            for (int nt = 0; nt < 8; nt++) {
                uint2 bb = *(const uint2*)&sK[(((ks << 3) + nt) * 32 + lane) * 2];
                uint32_t bf[2] = {bb.x, bb.y};
                mma8(s[nt], qa[ks], bf);
            }
        }
#pragma unroll
        for (int ks = 0; ks < 8; ks++) {
#pragma unroll
            for (int nt = 0; nt < 8; nt++) {
                uint2 bb = *(const uint2*)&sKp[(((ks << 3) + nt) * 32 + lane) * 2];
                uint32_t bf[2] = {bb.x, bb.y};
                mma8(s[nt], qpa[ks], bf);
            }
        }

        // ---- online softmax (thread owns rows g and g+8, 2 cols per ntile) ----
        float mx0 = -1e30f, mx1 = -1e30f;
#pragma unroll
        for (int nt = 0; nt < 8; nt++) {
            s[nt][0] *= SCORE_SCALE; s[nt][1] *= SCORE_SCALE;
            s[nt][2] *= SCORE_SCALE; s[nt][3] *= SCORE_SCALE;
            mx0 = fmaxf(mx0, fmaxf(s[nt][0], s[nt][1]));
            mx1 = fmaxf(mx1, fmaxf(s[nt][2], s[nt][3]));
        }
        mx0 = fmaxf(mx0, __shfl_xor_sync(0xffffffffu, mx0, 1));
        mx0 = fmaxf(mx0, __shfl_xor_sync(0xffffffffu, mx0, 2));
        mx1 = fmaxf(mx1, __shfl_xor_sync(0xffffffffu, mx1, 1));
        mx1 = fmaxf(mx1, __shfl_xor_sync(0xffffffffu, mx1, 2));
        const float mn0 = fmaxf(m0, mx0), mn1 = fmaxf(m1, mx1);
        const float a0 = __expf(m0 - mn0), a1 = __expf(m1 - mn1);
        m0 = mn0; m1 = mn1;
        float sum0 = 0.f, sum1 = 0.f;
        const int pbase = w << 10;
#pragma unroll
        for (int nt = 0; nt < 8; nt++) {
            float p0 = __expf(s[nt][0] - mn0);
            float p1 = __expf(s[nt][1] - mn0);
            float p2 = __expf(s[nt][2] - mn1);
            float p3 = __expf(s[nt][3] - mn1);
            sum0 += p0 + p1; sum1 += p2 + p3;
            o[nt][0] *= a0; o[nt][1] *= a0; o[nt][2] *= a1; o[nt][3] *= a1;
            // write P fragments (A-frag layout for PV); j local cols 2t, 2t+1
            int j0 = t << 1, j1 = j0 + 1;
            int l0i = (g << 2) + (j0 & 3), l1i = (g << 2) + (j1 & 3);
            int s0h = (j0 & 4) ? 2 : 0, s1h = (j1 & 4) ? 2 : 0;
            int kb = pbase + (nt << 7);   // (nt*32)*4
            sP[kb + l0i * 4 + s0h + 0] = f2tf(p0);
            sP[kb + l0i * 4 + s0h + 1] = f2tf(p2);
            sP[kb + l1i * 4 + s1h + 0] = f2tf(p1);
            sP[kb + l1i * 4 + s1h + 1] = f2tf(p3);
        }
        sum0 += __shfl_xor_sync(0xffffffffu, sum0, 1);
        sum0 += __shfl_xor_sync(0xffffffffu, sum0, 2);
        sum1 += __shfl_xor_sync(0xffffffffu, sum1, 1);
        sum1 += __shfl_xor_sync(0xffffffffu, sum1, 2);
        l0 = l0 * a0 + sum0;
        l1 = l1 * a1 + sum1;
        __syncwarp();

        // ---- O += P @ V ----
#pragma unroll
        for (int ks = 0; ks < 8; ks++) {
            uint4 pa4 = *(const uint4*)&sP[pbase + ((ks << 5) + lane) * 4];
            uint32_t pa[4] = {pa4.x, pa4.y, pa4.z, pa4.w};
#pragma unroll
            for (int nt = 0; nt < 8; nt++) {
                uint2 bb = *(const uint2*)&sV[(((ks << 3) + nt) * 32 + lane) * 2];
                uint32_t bf[2] = {bb.x, bb.y};
                mma8(o[nt], pa, bf);
            }
        }
        __syncwarp();
    }

    // ---- epilogue: normalize + store to g_ao ----
    const float inv0 = 1.f / l0, inv1 = 1.f / l1;
    const int r0 = (b << 10) + qbase + (w << 4) + g;
#pragma unroll
    for (int nt = 0; nt < 8; nt++) {
        int col = hoff + (nt << 3) + (t << 1);
        *(float2*)(g_ao + (size_t)r0 * 768 + col) =
            make_float2(o[nt][0] * inv0, o[nt][1] * inv0);
        *(float2*)(g_ao + (size_t)(r0 + 8) * 768 + col) =
            make_float2(o[nt][2] * inv1, o[nt][3] * inv1);
    }
}

// ---------------------------------------------------------------------------
extern "C" void kernel_launch(void* const* d_in, const int* in_sizes, int n_in,
                              void* d_out, int out_size)
{
    (void)in_sizes; (void)n_in; (void)out_size;
    const float* x     = (const float*)d_in[0];
    const float* pos   = (const float*)d_in[1];
    const float* w_qkv = (const float*)d_in[2];
    const float* w_qkp = (const float*)d_in[3];
    const float* w_out = (const float*)d_in[4];
    const float* b_out = (const float*)d_in[5];
    float* out = (float*)d_out;

    void *p_qkv, *p_pos, *p_ao;
    cudaGetSymbolAddress(&p_qkv, g_qkv);
    cudaGetSymbolAddress(&p_pos, g_pos2);
    cudaGetSymbolAddress(&p_ao,  g_ao);

    cudaFuncSetAttribute(attn_tc,
                         cudaFuncAttributeMaxDynamicSharedMemorySize, 65536);

    dim3 blk(128);
    // qkv = x @ w_qkv                [4096 x 2304]
    sgemm_tc<<<dim3(2304 / 128, 4096 / 128), blk>>>(
        x, w_qkv, nullptr, (float*)p_qkv, 4096, 2304, 768, 0);
    // qk_pos = pos @ w_qk_pos        [4096 x 1536]
    sgemm_tc<<<dim3(1536 / 128, 4096 / 128), blk>>>(
        pos, w_qkp, nullptr, (float*)p_pos, 4096, 1536, 768, 0);
    // fused dual-score attention -> g_ao
    attn_tc<<<dim3(16, 48), blk, 65536>>>();
    // out = ao @ w_out + b_out       [4096 x 768]
    sgemm_tc<<<dim3(768 / 128, 4096 / 128), blk>>>(
        (const float*)p_ao, w_out, b_out, out, 4096, 768, 768, 1);
}

// round 3
// speedup vs baseline: 1.3112x; 1.0184x over previous
#include <cuda_runtime.h>
#include <stdint.h>

// Problem constants
#define NB     4
#define NSEQ   1024
#define NHEADS 12
#define NINNER 768   // 12*64
// combined score scale = 0.5 / sqrt(768)
#define SCORE_SCALE 0.018042195912175807f

// Scratch (static device memory: allowed; cudaMalloc is not)
__device__ __align__(16) float g_qkv [NB * NSEQ * 3 * NINNER]; // tf32 bits
__device__ __align__(16) float g_pos2[NB * NSEQ * 2 * NINNER]; // tf32 bits
__device__ __align__(16) float g_ao  [NB * NSEQ * NINNER];     // tf32 bits
// tf32-rounded copies of the inputs
__device__ __align__(16) float g_tx   [NB * NSEQ * 768];
__device__ __align__(16) float g_tpos [NB * NSEQ * 768];
__device__ __align__(16) float g_twqkv[768 * 2304];
__device__ __align__(16) float g_twqkp[768 * 1536];
__device__ __align__(16) float g_twout[768 * 768];

// ---------------------------------------------------------------------------
__device__ __forceinline__ uint32_t f2tf(float x) {
    uint32_t u;
    asm("cvt.rna.tf32.f32 %0, %1;" : "=r"(u) : "f"(x));
    return u;
}
__device__ __forceinline__ float f2tff(float x) { return __uint_as_float(f2tf(x)); }

// D += A@B, m16n8k8, A row-major, B col-major, tf32 in / f32 acc
__device__ __forceinline__ void mma8(float* d, const uint32_t* a, const uint32_t* b) {
    asm volatile(
        "mma.sync.aligned.m16n8k8.row.col.f32.tf32.tf32.f32 "
        "{%0,%1,%2,%3}, {%4,%5,%6,%7}, {%8,%9}, {%0,%1,%2,%3};\n"
        : "+f"(d[0]), "+f"(d[1]), "+f"(d[2]), "+f"(d[3])
        : "r"(a[0]), "r"(a[1]), "r"(a[2]), "r"(a[3]), "r"(b[0]), "r"(b[1]));
}

// ---------------------------------------------------------------------------
// Pre-pass: round all fp32 inputs to tf32 bit patterns (RNA), float4-wide.
// ---------------------------------------------------------------------------
#define N4_X    786432   // 4096*768/4
#define N4_WQKV 442368   // 768*2304/4
#define N4_WQKP 294912   // 768*1536/4
#define N4_WOUT 147456   // 768*768/4
#define N4_TOT  (N4_X + N4_X + N4_WQKV + N4_WQKP + N4_WOUT)

__global__ void __launch_bounds__(256) cvt_all(
    const float4* __restrict__ x, const float4* __restrict__ pos,
    const float4* __restrict__ wqkv, const float4* __restrict__ wqkp,
    const float4* __restrict__ wout)
{
    int i = blockIdx.x * 256 + threadIdx.x;
    const float4* s; float4* d; int off;
    if (i < N4_X)                      { s = x;    d = (float4*)g_tx;    off = i; }
    else if (i < 2*N4_X)               { s = pos;  d = (float4*)g_tpos;  off = i - N4_X; }
    else if (i < 2*N4_X+N4_WQKV)       { s = wqkv; d = (float4*)g_twqkv; off = i - 2*N4_X; }
    else if (i < 2*N4_X+N4_WQKV+N4_WQKP){ s = wqkp; d = (float4*)g_twqkp; off = i - 2*N4_X - N4_WQKV; }
    else if (i < N4_TOT)               { s = wout; d = (float4*)g_twout; off = i - 2*N4_X - N4_WQKV - N4_WQKP; }
    else return;
    float4 v = s[off];
    v.x = f2tff(v.x); v.y = f2tff(v.y); v.z = f2tff(v.z); v.w = f2tff(v.w);
    d[off] = v;
}

// ---------------------------------------------------------------------------
// Pipelined tensor-core SGEMM (inputs already tf32 bits).
// Block 128 thr / 4 warps (2x2), tile 128x128, BK=16, warp tile 64x64.
// Double-buffered smem in mma fragment layout; register prefetch one tile
// ahead; one __syncthreads per iteration.
// mode: 0 = plain, 1 = +bias (fp32 out), 2 = tf32-round output.
// ---------------------------------------------------------------------------
__device__ __forceinline__ void ldg_tile(
    const float* __restrict__ A, const float* __restrict__ Bm,
    int tid, int bm, int bn, int K, int Nn, int k0,
    float4* ar, float4* br)
{
#pragma unroll
    for (int i = 0; i < 4; i++) {
        int lin = tid + (i << 7);
        int row = lin >> 2, kc = (lin & 3) << 2;
        ar[i] = *(const float4*)(A + (size_t)(bm + row) * K + k0 + kc);
        int krow = lin >> 5, c4 = (lin & 31) << 2;
        br[i] = *(const float4*)(Bm + (size_t)(k0 + krow) * Nn + bn + c4);
    }
}

__device__ __forceinline__ void sts_tile(
    uint32_t* __restrict__ As, uint32_t* __restrict__ Bs,
    int tid, const float4* ar, const float4* br)
{
#pragma unroll
    for (int i = 0; i < 4; i++) {
        int lin = tid + (i << 7);
        int row = lin >> 2, kc = (lin & 3) << 2;
        int kstep = kc >> 3;
        int mt    = row >> 4;
        int base  = ((kstep << 3) + mt) * 32 + ((row & 7) << 2);
        int slot  = ((row >> 3) & 1) | ((kc & 4) ? 2 : 0);
        As[(base + 0) * 4 + slot] = __float_as_uint(ar[i].x);
        As[(base + 1) * 4 + slot] = __float_as_uint(ar[i].y);
        As[(base + 2) * 4 + slot] = __float_as_uint(ar[i].z);
        As[(base + 3) * 4 + slot] = __float_as_uint(ar[i].w);
        int krow = lin >> 5, c4 = (lin & 31) << 2;
        int kstep2 = krow >> 3, slot2 = (krow >> 2) & 1;
        int nt    = c4 >> 3;
        int lbase = ((c4 & 7) << 2) + (krow & 3);
        int base2 = ((kstep2 << 4) + nt) * 32;
        Bs[(base2 + lbase + 0) * 2 + slot2] = __float_as_uint(br[i].x);
        Bs[(base2 + lbase + 4) * 2 + slot2] = __float_as_uint(br[i].y);
        Bs[(base2 + lbase + 8) * 2 + slot2] = __float_as_uint(br[i].z);
        Bs[(base2 + lbase + 12) * 2 + slot2] = __float_as_uint(br[i].w);
    }
}

__global__ void __launch_bounds__(128, 2) sgemm_tc(
    const float* __restrict__ A, const float* __restrict__ Bm,
    const float* __restrict__ bias, float* __restrict__ C,
    int M, int Nn, int K, int mode)
{
    __shared__ uint32_t As[2][2048];
    __shared__ uint32_t Bs[2][2048];

    const int tid  = threadIdx.x;
    const int lane = tid & 31, warp = tid >> 5;
    const int wm = warp >> 1, wn = warp & 1;
    const int g = lane >> 2, t = lane & 3;
    const int bm = blockIdx.y << 7, bn = blockIdx.x << 7;
    const int nk = K >> 4;

    float acc[4][8][4];
#pragma unroll
    for (int mt = 0; mt < 4; mt++)
#pragma unroll
        for (int nt = 0; nt < 8; nt++)
#pragma unroll
            for (int i = 0; i < 4; i++) acc[mt][nt][i] = 0.f;

    float4 ar[4], br[4];
    // prologue
    ldg_tile(A, Bm, tid, bm, bn, K, Nn, 0, ar, br);
    sts_tile(As[0], Bs[0], tid, ar, br);
    ldg_tile(A, Bm, tid, bm, bn, K, Nn, 16, ar, br);
    __syncthreads();

    for (int it = 0; it < nk; it++) {
        const int cur = it & 1;
        if (it + 1 < nk) {
            sts_tile(As[cur ^ 1], Bs[cur ^ 1], tid, ar, br);
            if (it + 2 < nk)
                ldg_tile(A, Bm, tid, bm, bn, K, Nn, (it + 2) << 4, ar, br);
        }
        const uint32_t* Ac = As[cur];
        const uint32_t* Bc = Bs[cur];
#pragma unroll
        for (int ks = 0; ks < 2; ks++) {
            uint32_t bf[8][2];
#pragma unroll
            for (int nt = 0; nt < 8; nt++) {
                int ntg = (wn << 3) + nt;
                uint2 bb = *(const uint2*)&Bc[(((ks << 4) + ntg) * 32 + lane) * 2];
                bf[nt][0] = bb.x; bf[nt][1] = bb.y;
            }
#pragma unroll
            for (int mt = 0; mt < 4; mt++) {
                int mtg = (wm << 2) + mt;
                uint4 aa = *(const uint4*)&Ac[(((ks << 3) + mtg) * 32 + lane) * 4];
                uint32_t af[4] = {aa.x, aa.y, aa.z, aa.w};
#pragma unroll
                for (int nt = 0; nt < 8; nt++) mma8(acc[mt][nt], af, bf[nt]);
            }
        }
        __syncthreads();
    }

    // epilogue
#pragma unroll
    for (int mt = 0; mt < 4; mt++) {
#pragma unroll
        for (int nt = 0; nt < 8; nt++) {
            int row0 = bm + (wm << 6) + (mt << 4) + g;
            int col0 = bn + (wn << 6) + (nt << 3) + (t << 1);
            float v0 = acc[mt][nt][0], v1 = acc[mt][nt][1];
            float v2 = acc[mt][nt][2], v3 = acc[mt][nt][3];
            if (mode == 1) {
                float2 bb = *(const float2*)(bias + col0);
                v0 += bb.x; v1 += bb.y; v2 += bb.x; v3 += bb.y;
            } else if (mode == 2) {
                v0 = f2tff(v0); v1 = f2tff(v1); v2 = f2tff(v2); v3 = f2tff(v3);
            }
            *(float2*)(C + (size_t)row0 * Nn + col0) = make_float2(v0, v1);
            *(float2*)(C + (size_t)(row0 + 8) * Nn + col0) = make_float2(v2, v3);
        }
    }
}

// ---------------------------------------------------------------------------
// Fused dual-score flash attention, tensor-core version.
// (Same structure as R2; all cvt removed — g_qkv/g_pos2 are pre-rounded.)
// ---------------------------------------------------------------------------
__global__ void __launch_bounds__(128, 2) attn_tc()
{
    extern __shared__ uint32_t sm[];
    uint32_t* sK  = sm;            // [kstep(d)][ntile(j)][lane][2]
    uint32_t* sKp = sm + 4096;
    uint32_t* sV  = sm + 8192;     // [kstep(j)][ntile(d)][lane][2]
    uint32_t* sP  = sm + 12288;    // per-warp: [kstep(j)][lane][4]

    const int tid  = threadIdx.x;
    const int lane = tid & 31, w = tid >> 5;
    const int g = lane >> 2, t = lane & 3;
    const int bh = blockIdx.y;
    const int b = bh / NHEADS, h = bh % NHEADS;
    const int qbase = blockIdx.x << 6;
    const int hoff = h << 6;

    // ---- preload Q / Qpos fragments (16 rows per warp, full d=64) ----
    uint32_t qa[8][4], qpa[8][4];
    {
        const int r0 = (b << 10) + qbase + (w << 4);
#pragma unroll
        for (int ks = 0; ks < 8; ks++) {
#pragma unroll
            for (int s = 0; s < 4; s++) {
                int row = r0 + g + ((s & 1) << 3);
                int col = (ks << 3) + t + ((s & 2) << 1);
                qa[ks][s]  = __float_as_uint(g_qkv [(size_t)row * 2304 + hoff + col]);
                qpa[ks][s] = __float_as_uint(g_pos2[(size_t)row * 1536 + hoff + col]);
            }
        }
    }

    float o[8][4];
#pragma unroll
    for (int nt = 0; nt < 8; nt++)
#pragma unroll
        for (int i = 0; i < 4; i++) o[nt][i] = 0.f;
    float m0 = -1e30f, m1 = -1e30f, l0 = 0.f, l1 = 0.f;

    for (int kt = 0; kt < 16; kt++) {
        const int kbase = kt << 6;
        const size_t krow = (size_t)((b << 10) + kbase);

        __syncthreads();
#pragma unroll
        for (int i = 0; i < 8; i++) {
            int lin = tid + (i << 7);      // 0..1023
            int j  = lin >> 4;             // kv row 0..63
            int c4 = (lin & 15) << 2;      // d 0,4,..,60
            float4 kv = *(const float4*)(g_qkv  + (krow + j) * 2304 + 768  + hoff + c4);
            float4 kp = *(const float4*)(g_pos2 + (krow + j) * 1536 + 768  + hoff + c4);
            float4 vv = *(const float4*)(g_qkv  + (krow + j) * 2304 + 1536 + hoff + c4);
            float kvv[4] = {kv.x, kv.y, kv.z, kv.w};
            float kpv[4] = {kp.x, kp.y, kp.z, kp.w};
            float vvv[4] = {vv.x, vv.y, vv.z, vv.w};
#pragma unroll
            for (int jj = 0; jj < 4; jj++) {
                int d = c4 + jj;
                int ia = ((((d >> 3) << 3) + (j >> 3)) * 32 + ((j & 7) << 2) + (d & 3)) * 2
                         + ((d >> 2) & 1);
                sK[ia]  = __float_as_uint(kvv[jj]);
                sKp[ia] = __float_as_uint(kpv[jj]);
                int iv = ((((j >> 3) << 3) + (d >> 3)) * 32 + ((d & 7) << 2) + (j & 3)) * 2
                         + ((j >> 2) & 1);
                sV[iv] = __float_as_uint(vvv[jj]);
            }
        }
        __syncthreads();

        // ---- S = Q@K^T + Qp@Kp^T ----
        float s[8][4];
#pragma unroll
        for (int nt = 0; nt < 8; nt++)
#pragma unroll
            for (int i = 0; i < 4; i++) s[nt][i] = 0.f;
#pragma unroll
        for (int ks = 0; ks < 8; ks++) {
#pragma unroll
            for (int nt = 0; nt < 8; nt++) {
                uint2 bb = *(const uint2*)&sK[(((ks << 3) + nt) * 32 + lane) * 2];
                uint32_t bf[2] = {bb.x, bb.y};
                mma8(s[nt], qa[ks], bf);
            }
        }
#pragma unroll
        for (int ks = 0; ks < 8; ks++) {
#pragma unroll
            for (int nt = 0; nt < 8; nt++) {
                uint2 bb = *(const uint2*)&sKp[(((ks << 3) + nt) * 32 + lane) * 2];
                uint32_t bf[2] = {bb.x, bb.y};
                mma8(s[nt], qpa[ks], bf);
            }
        }

        // ---- online softmax ----
        float mx0 = -1e30f, mx1 = -1e30f;
#pragma unroll
        for (int nt = 0; nt < 8; nt++) {
            s[nt][0] *= SCORE_SCALE; s[nt][1] *= SCORE_SCALE;
            s[nt][2] *= SCORE_SCALE; s[nt][3] *= SCORE_SCALE;
            mx0 = fmaxf(mx0, fmaxf(s[nt][0], s[nt][1]));
            mx1 = fmaxf(mx1, fmaxf(s[nt][2], s[nt][3]));
        }
        mx0 = fmaxf(mx0, __shfl_xor_sync(0xffffffffu, mx0, 1));
        mx0 = fmaxf(mx0, __shfl_xor_sync(0xffffffffu, mx0, 2));
        mx1 = fmaxf(mx1, __shfl_xor_sync(0xffffffffu, mx1, 1));
        mx1 = fmaxf(mx1, __shfl_xor_sync(0xffffffffu, mx1, 2));
        const float mn0 = fmaxf(m0, mx0), mn1 = fmaxf(m1, mx1);
        const float a0 = __expf(m0 - mn0), a1 = __expf(m1 - mn1);
        m0 = mn0; m1 = mn1;
        float sum0 = 0.f, sum1 = 0.f;
        const int pbase = w << 10;
#pragma unroll
        for (int nt = 0; nt < 8; nt++) {
            float p0 = __expf(s[nt][0] - mn0);
            float p1 = __expf(s[nt][1] - mn0);
            float p2 = __expf(s[nt][2] - mn1);
            float p3 = __expf(s[nt][3] - mn1);
            sum0 += p0 + p1; sum1 += p2 + p3;
            o[nt][0] *= a0; o[nt][1] *= a0; o[nt][2] *= a1; o[nt][3] *= a1;
            int j0 = t << 1, j1 = j0 + 1;
            int l0i = (g << 2) + (j0 & 3), l1i = (g << 2) + (j1 & 3);
            int s0h = (j0 & 4) ? 2 : 0, s1h = (j1 & 4) ? 2 : 0;
            int kb = pbase + (nt << 7);
            sP[kb + l0i * 4 + s0h + 0] = f2tf(p0);
            sP[kb + l0i * 4 + s0h + 1] = f2tf(p2);
            sP[kb + l1i * 4 + s1h + 0] = f2tf(p1);
            sP[kb + l1i * 4 + s1h + 1] = f2tf(p3);
        }
        sum0 += __shfl_xor_sync(0xffffffffu, sum0, 1);
        sum0 += __shfl_xor_sync(0xffffffffu, sum0, 2);
        sum1 += __shfl_xor_sync(0xffffffffu, sum1, 1);
        sum1 += __shfl_xor_sync(0xffffffffu, sum1, 2);
        l0 = l0 * a0 + sum0;
        l1 = l1 * a1 + sum1;
        __syncwarp();

        // ---- O += P @ V ----
#pragma unroll
        for (int ks = 0; ks < 8; ks++) {
            uint4 pa4 = *(const uint4*)&sP[pbase + ((ks << 5) + lane) * 4];
            uint32_t pa[4] = {pa4.x, pa4.y, pa4.z, pa4.w};
#pragma unroll
            for (int nt = 0; nt < 8; nt++) {
                uint2 bb = *(const uint2*)&sV[(((ks << 3) + nt) * 32 + lane) * 2];
                uint32_t bf[2] = {bb.x, bb.y};
                mma8(o[nt], pa, bf);
            }
        }
        __syncwarp();
    }

    // ---- epilogue: normalize + store tf32-rounded to g_ao ----
    const float inv0 = 1.f / l0, inv1 = 1.f / l1;
    const int r0 = (b << 10) + qbase + (w << 4) + g;
#pragma unroll
    for (int nt = 0; nt < 8; nt++) {
        int col = hoff + (nt << 3) + (t << 1);
        *(float2*)(g_ao + (size_t)r0 * 768 + col) =
            make_float2(f2tff(o[nt][0] * inv0), f2tff(o[nt][1] * inv0));
        *(float2*)(g_ao + (size_t)(r0 + 8) * 768 + col) =
            make_float2(f2tff(o[nt][2] * inv1), f2tff(o[nt][3] * inv1));
    }
}

// ---------------------------------------------------------------------------
extern "C" void kernel_launch(void* const* d_in, const int* in_sizes, int n_in,
                              void* d_out, int out_size)
{
    (void)in_sizes; (void)n_in; (void)out_size;
    const float* x     = (const float*)d_in[0];
    const float* pos   = (const float*)d_in[1];
    const float* w_qkv = (const float*)d_in[2];
    const float* w_qkp = (const float*)d_in[3];
    const float* w_out = (const float*)d_in[4];
    const float* b_out = (const float*)d_in[5];
    float* out = (float*)d_out;

    void *p_qkv, *p_pos, *p_ao, *p_tx, *p_tpos, *p_twqkv, *p_twqkp, *p_twout;
    cudaGetSymbolAddress(&p_qkv,  g_qkv);
    cudaGetSymbolAddress(&p_pos,  g_pos2);
    cudaGetSymbolAddress(&p_ao,   g_ao);
    cudaGetSymbolAddress(&p_tx,   g_tx);
    cudaGetSymbolAddress(&p_tpos, g_tpos);
    cudaGetSymbolAddress(&p_twqkv, g_twqkv);
    cudaGetSymbolAddress(&p_twqkp, g_twqkp);
    cudaGetSymbolAddress(&p_twout, g_twout);

    cudaFuncSetAttribute(attn_tc,
                         cudaFuncAttributeMaxDynamicSharedMemorySize, 65536);

    // 0) round all inputs to tf32 once
    cvt_all<<<(N4_TOT + 255) / 256, 256>>>(
        (const float4*)x, (const float4*)pos,
        (const float4*)w_qkv, (const float4*)w_qkp, (const float4*)w_out);

    dim3 blk(128);
    // 1) qkv = x @ w_qkv            [4096 x 2304], output tf32-rounded
    sgemm_tc<<<dim3(2304 / 128, 4096 / 128), blk>>>(
        (const float*)p_tx, (const float*)p_twqkv, nullptr, (float*)p_qkv,
        4096, 2304, 768, 2);
    // 2) qk_pos = pos @ w_qk_pos    [4096 x 1536], output tf32-rounded
    sgemm_tc<<<dim3(1536 / 128, 4096 / 128), blk>>>(
        (const float*)p_tpos, (const float*)p_twqkp, nullptr, (float*)p_pos,
        4096, 1536, 768, 2);
    // 3) fused dual-score attention -> g_ao (tf32-rounded)
    attn_tc<<<dim3(16, 48), blk, 65536>>>();
    // 4) out = ao @ w_out + b_out   [4096 x 768], fp32 + bias
    sgemm_tc<<<dim3(768 / 128, 4096 / 128), blk>>>(
        (const float*)p_ao, (const float*)p_twout, b_out, out,
        4096, 768, 768, 1);
}

// round 4
// speedup vs baseline: 2.8742x; 2.1921x over previous
#include <cuda_runtime.h>
#include <stdint.h>

// Problem constants
#define NB     4
#define NSEQ   1024
#define NHEADS 12
#define NINNER 768
// combined score scale = 0.5 / sqrt(768)
#define SCORE_SCALE 0.018042195912175807f

// ---------------------------------------------------------------------------
// Fragment-layout global buffers (all tf32 bits stored as float)
// A-frag (m16n8k8): float idx = ((mt*K8 + ks)*32 + (r&7)*4+(c&3))*4
//                              + ((r>>3)&1) + (((c>>2)&1)<<1)
// B-frag pair:      float idx = ((nt*K16 + ks2)*32 + (n&7)*4+(k&3))*4
//                              + (((k>>3)&1)<<1) + ((k>>2)&1)
// ---------------------------------------------------------------------------
__device__ __align__(16) float g_txA  [4096 * 768];    // x, A-frag (K8=96)
__device__ __align__(16) float g_tposA[4096 * 768];    // pos, A-frag
__device__ __align__(16) float g_wqkvB[768 * 2304];    // B-frag (K16=48)
__device__ __align__(16) float g_wqkpB[768 * 1536];
__device__ __align__(16) float g_woutB[768 * 768];
// per-(b,h) attention fragments, 65536 floats per bh (48 bh)
__device__ __align__(16) float g_QF [48 * 65536];  // A-frag over [n=1024, d=64]
__device__ __align__(16) float g_QPF[48 * 65536];
__device__ __align__(16) float g_KF [48 * 65536];  // B-frag, k-dim=d, n-dim=j
__device__ __align__(16) float g_KPF[48 * 65536];
__device__ __align__(16) float g_VF [48 * 65536];  // B-frag, k-dim=j, n-dim=d
__device__ __align__(16) float g_AOF[4096 * 768];  // attn out, A-frag (K8=96)

// ---------------------------------------------------------------------------
__device__ __forceinline__ uint32_t f2tf(float x) {
    uint32_t u;
    asm("cvt.rna.tf32.f32 %0, %1;" : "=r"(u) : "f"(x));
    return u;
}
__device__ __forceinline__ float f2tff(float x) { return __uint_as_float(f2tf(x)); }

__device__ __forceinline__ void mma8v(float* d,
    uint32_t a0, uint32_t a1, uint32_t a2, uint32_t a3,
    uint32_t b0, uint32_t b1) {
    asm volatile(
        "mma.sync.aligned.m16n8k8.row.col.f32.tf32.tf32.f32 "
        "{%0,%1,%2,%3}, {%4,%5,%6,%7}, {%8,%9}, {%0,%1,%2,%3};\n"
        : "+f"(d[0]), "+f"(d[1]), "+f"(d[2]), "+f"(d[3])
        : "r"(a0), "r"(a1), "r"(a2), "r"(a3), "r"(b0), "r"(b1));
}

// scatter-offset helpers (single source of truth for producer & consumer)
__device__ __forceinline__ int a_off(int r, int c, int K8) {
    return (((r >> 4) * K8 + (c >> 3)) * 32 + ((r & 7) << 2) + (c & 3)) * 4
           + ((r >> 3) & 1) + (((c >> 2) & 1) << 1);
}
__device__ __forceinline__ int q_off(int n, int d) {   // A-frag, K8=8 (d)
    return (((n >> 4) * 8 + (d >> 3)) * 32 + ((n & 7) << 2) + (d & 3)) * 4
           + ((n >> 3) & 1) + (((d >> 2) & 1) << 1);
}
__device__ __forceinline__ int k_off(int j, int d) {   // B-frag, k=d(K16=4), n=j
    return (((j >> 3) * 4 + (d >> 4)) * 32 + ((j & 7) << 2) + (d & 3)) * 4
           + (((d >> 3) & 1) << 1) + ((d >> 2) & 1);
}
__device__ __forceinline__ int v_off(int j, int d) {   // B-frag, k=j(K16=64), n=d
    return (((d >> 3) * 64 + (j >> 4)) * 32 + ((d & 7) << 2) + (j & 3)) * 4
           + (((j >> 3) & 1) << 1) + ((j >> 2) & 1);
}

// ---------------------------------------------------------------------------
// Permutation pre-passes (fp32 -> tf32 bits in fragment layout)
// ---------------------------------------------------------------------------
__global__ void __launch_bounds__(256) permA_k(
    const float* __restrict__ S, uint4* __restrict__ D, int K)
{
    int i = blockIdx.x * 256 + threadIdx.x;       // one output uint4
    int lane = i & 31, rest = i >> 5;
    int K8 = K >> 3;
    int tM = rest / K8, ks = rest - tM * K8;
    int r0 = (tM << 4) + (lane >> 2);
    int c0 = (ks << 3) + (lane & 3);
    const float* p = S + (size_t)r0 * K + c0;
    uint4 v;
    v.x = f2tf(p[0]);
    v.y = f2tf(p[(size_t)8 * K]);
    v.z = f2tf(p[4]);
    v.w = f2tf(p[(size_t)8 * K + 4]);
    D[i] = v;
}

__global__ void __launch_bounds__(256) permB_k(
    const float* __restrict__ S, uint4* __restrict__ D, int K, int Nn)
{
    int i = blockIdx.x * 256 + threadIdx.x;
    int lane = i & 31, rest = i >> 5;
    int K16 = K >> 4;
    int tN = rest / K16, ks2 = rest - tN * K16;
    int n  = (tN << 3) + (lane >> 2);
    int k0 = (ks2 << 4) + (lane & 3);
    const float* p = S + (size_t)k0 * Nn + n;
    uint4 v;
    v.x = f2tf(p[0]);
    v.y = f2tf(p[(size_t)4 * Nn]);
    v.z = f2tf(p[(size_t)8 * Nn]);
    v.w = f2tf(p[(size_t)12 * Nn]);
    D[i] = v;
}

// ---------------------------------------------------------------------------
// Fragment-direct GEMM: no smem, no syncs. Block 128 thr (2x2 warps),
// tile 128x128, warp tile 64x64. Per BK16 iter: 16 LDG.128 + 64 mma / warp.
// mode 0: scatter q/k/v to QF/KF/VF        (GEMM1, N=2304)
// mode 1: scatter q_pos/k_pos to QPF/KPF   (GEMM2, N=1536)
// mode 2: C = acc + bias, row-major fp32   (GEMM3)
// ---------------------------------------------------------------------------
__global__ void __launch_bounds__(128, 2) gemm_frag(
    const uint4* __restrict__ Ap, const uint4* __restrict__ Bp,
    const float* __restrict__ bias, float* __restrict__ C,
    int K, int Nn, int mode)
{
    const int tid = threadIdx.x;
    const int lane = tid & 31, warp = tid >> 5;
    const int wm = warp >> 1, wn = warp & 1;
    const int g = lane >> 2, t = lane & 3;
    const int bm = blockIdx.y << 7, bn = blockIdx.x << 7;
    const int K8 = K >> 3, K16 = K >> 4;
    const int tM0 = (bm >> 4) + (wm << 2);
    const int tN0 = (bn >> 3) + (wn << 3);

    float acc[4][8][4];
#pragma unroll
    for (int mt = 0; mt < 4; mt++)
#pragma unroll
        for (int nt = 0; nt < 8; nt++)
#pragma unroll
            for (int i = 0; i < 4; i++) acc[mt][nt][i] = 0.f;

    for (int it = 0; it < K16; it++) {
        uint4 bfr[8], afr[4][2];
#pragma unroll
        for (int nt = 0; nt < 8; nt++)
            bfr[nt] = Bp[((tN0 + nt) * K16 + it) * 32 + lane];
#pragma unroll
        for (int mt = 0; mt < 4; mt++) {
            afr[mt][0] = Ap[((tM0 + mt) * K8 + 2 * it) * 32 + lane];
            afr[mt][1] = Ap[((tM0 + mt) * K8 + 2 * it + 1) * 32 + lane];
        }
#pragma unroll
        for (int kk = 0; kk < 2; kk++)
#pragma unroll
            for (int mt = 0; mt < 4; mt++)
#pragma unroll
                for (int nt = 0; nt < 8; nt++)
                    mma8v(acc[mt][nt],
                          afr[mt][kk].x, afr[mt][kk].y, afr[mt][kk].z, afr[mt][kk].w,
                          kk ? bfr[nt].z : bfr[nt].x,
                          kk ? bfr[nt].w : bfr[nt].y);
    }

    if (mode == 2) {
#pragma unroll
        for (int mt = 0; mt < 4; mt++)
#pragma unroll
            for (int nt = 0; nt < 8; nt++) {
                int row0 = bm + (wm << 6) + (mt << 4) + g;
                int col0 = bn + (wn << 6) + (nt << 3) + (t << 1);
                float2 bb = *(const float2*)(bias + col0);
                *(float2*)(C + (size_t)row0 * Nn + col0) =
                    make_float2(acc[mt][nt][0] + bb.x, acc[mt][nt][1] + bb.y);
                *(float2*)(C + (size_t)(row0 + 8) * Nn + col0) =
                    make_float2(acc[mt][nt][2] + bb.x, acc[mt][nt][3] + bb.y);
            }
        return;
    }

    // scatter epilogue into attention fragment layouts
#pragma unroll
    for (int mt = 0; mt < 4; mt++)
#pragma unroll
        for (int nt = 0; nt < 8; nt++) {
            int row0 = bm + (wm << 6) + (mt << 4) + g;
            int col0 = bn + (wn << 6) + (nt << 3) + (t << 1);
#pragma unroll
            for (int e = 0; e < 4; e++) {
                int m  = row0 + ((e >> 1) << 3);
                int cg = col0 + (e & 1);
                float tv = f2tff(acc[mt][nt][e]);
                int b_ = m >> 10, n_ = m & 1023;
                int sec = (cg >= 1536) ? 2 : (cg >= 768 ? 1 : 0);
                int cc = cg - sec * 768;
                int h = cc >> 6, d = cc & 63;
                size_t base = (size_t)(b_ * 12 + h) * 65536;
                if (mode == 0) {
                    if (sec == 0)      g_QF[base + q_off(n_, d)] = tv;
                    else if (sec == 1) g_KF[base + k_off(n_, d)] = tv;
                    else               g_VF[base + v_off(n_, d)] = tv;
                } else {
                    if (sec == 0)      g_QPF[base + q_off(n_, d)] = tv;
                    else               g_KPF[base + k_off(n_, d)] = tv;
                }
            }
        }
}

// ---------------------------------------------------------------------------
// Fragment-direct dual-score flash attention.
// Grid (8 q-blocks, 48 bh), block 128 thr / 4 warps. Warp owns 32 q-rows
// (2 m16 stripes). Q frags in regs; Qp streamed; K/Kp/V frags via LDG
// (L1-shared across warps). Smem only for P transpose (8 KB/warp).
// ---------------------------------------------------------------------------
__global__ void __launch_bounds__(128) attn_frag()
{
    __shared__ uint32_t sP[4][2][1024];   // [warp][stripe][jks*128 + lane*4 + slot]

    const int tid = threadIdx.x;
    const int lane = tid & 31, w = tid >> 5;
    const int g = lane >> 2, t = lane & 3;
    const int bh = blockIdx.y;
    const size_t bh16 = (size_t)bh * 16384;            // uint4 units per bh
    const uint4* QF4  = (const uint4*)g_QF  + bh16;
    const uint4* QPF4 = (const uint4*)g_QPF + bh16;
    const uint4* KF4  = (const uint4*)g_KF  + bh16;
    const uint4* KPF4 = (const uint4*)g_KPF + bh16;
    const uint4* VF4  = (const uint4*)g_VF  + bh16;
    const int tq0 = blockIdx.x * 8 + w * 2;

    uint4 qa[2][8];
#pragma unroll
    for (int st = 0; st < 2; st++)
#pragma unroll
        for (int ks = 0; ks < 8; ks++)
            qa[st][ks] = QF4[((tq0 + st) * 8 + ks) * 32 + lane];

    float o[2][8][4];
    float mrow[2][2], lrow[2][2];
#pragma unroll
    for (int st = 0; st < 2; st++) {
        mrow[st][0] = -1e30f; mrow[st][1] = -1e30f;
        lrow[st][0] = 0.f;    lrow[st][1] = 0.f;
#pragma unroll
        for (int nt = 0; nt < 8; nt++)
#pragma unroll
            for (int i = 0; i < 4; i++) o[st][nt][i] = 0.f;
    }

    for (int kt = 0; kt < 16; kt++) {
        float s[2][8][4];
#pragma unroll
        for (int st = 0; st < 2; st++)
#pragma unroll
            for (int tj = 0; tj < 8; tj++)
#pragma unroll
                for (int i = 0; i < 4; i++) s[st][tj][i] = 0.f;

        // ---- content scores: S += Q @ K^T ----
#pragma unroll
        for (int ks2 = 0; ks2 < 4; ks2++) {
#pragma unroll
            for (int tj = 0; tj < 8; tj++) {
                uint4 kf = KF4[(((kt << 3) + tj) * 4 + ks2) * 32 + lane];
                mma8v(s[0][tj], qa[0][2*ks2].x, qa[0][2*ks2].y, qa[0][2*ks2].z, qa[0][2*ks2].w, kf.x, kf.y);
                mma8v(s[0][tj], qa[0][2*ks2+1].x, qa[0][2*ks2+1].y, qa[0][2*ks2+1].z, qa[0][2*ks2+1].w, kf.z, kf.w);
                mma8v(s[1][tj], qa[1][2*ks2].x, qa[1][2*ks2].y, qa[1][2*ks2].z, qa[1][2*ks2].w, kf.x, kf.y);
                mma8v(s[1][tj], qa[1][2*ks2+1].x, qa[1][2*ks2+1].y, qa[1][2*ks2+1].z, qa[1][2*ks2+1].w, kf.z, kf.w);
            }
        }
        // ---- positional scores: S += Qp @ Kp^T (Qp streamed from L1/L2) ----
#pragma unroll
        for (int ks2 = 0; ks2 < 4; ks2++) {
            uint4 qp00 = QPF4[((tq0)     * 8 + 2 * ks2)     * 32 + lane];
            uint4 qp01 = QPF4[((tq0)     * 8 + 2 * ks2 + 1) * 32 + lane];
            uint4 qp10 = QPF4[((tq0 + 1) * 8 + 2 * ks2)     * 32 + lane];
            uint4 qp11 = QPF4[((tq0 + 1) * 8 + 2 * ks2 + 1) * 32 + lane];
#pragma unroll
            for (int tj = 0; tj < 8; tj++) {
                uint4 kp = KPF4[(((kt << 3) + tj) * 4 + ks2) * 32 + lane];
                mma8v(s[0][tj], qp00.x, qp00.y, qp00.z, qp00.w, kp.x, kp.y);
                mma8v(s[0][tj], qp01.x, qp01.y, qp01.z, qp01.w, kp.z, kp.w);
                mma8v(s[1][tj], qp10.x, qp10.y, qp10.z, qp10.w, kp.x, kp.y);
                mma8v(s[1][tj], qp11.x, qp11.y, qp11.z, qp11.w, kp.z, kp.w);
            }
        }

        // ---- online softmax per stripe ----
#pragma unroll
        for (int st = 0; st < 2; st++) {
            float mx0 = -1e30f, mx1 = -1e30f;
#pragma unroll
            for (int tj = 0; tj < 8; tj++) {
                s[st][tj][0] *= SCORE_SCALE; s[st][tj][1] *= SCORE_SCALE;
                s[st][tj][2] *= SCORE_SCALE; s[st][tj][3] *= SCORE_SCALE;
                mx0 = fmaxf(mx0, fmaxf(s[st][tj][0], s[st][tj][1]));
                mx1 = fmaxf(mx1, fmaxf(s[st][tj][2], s[st][tj][3]));
            }
            mx0 = fmaxf(mx0, __shfl_xor_sync(0xffffffffu, mx0, 1));
            mx0 = fmaxf(mx0, __shfl_xor_sync(0xffffffffu, mx0, 2));
            mx1 = fmaxf(mx1, __shfl_xor_sync(0xffffffffu, mx1, 1));
            mx1 = fmaxf(mx1, __shfl_xor_sync(0xffffffffu, mx1, 2));
            const float mn0 = fmaxf(mrow[st][0], mx0);
            const float mn1 = fmaxf(mrow[st][1], mx1);
            const float a0 = __expf(mrow[st][0] - mn0);
            const float a1 = __expf(mrow[st][1] - mn1);
            mrow[st][0] = mn0; mrow[st][1] = mn1;
            float sm0 = 0.f, sm1 = 0.f;
            const int j0 = t << 1, j1 = j0 + 1;
            const int i0 = (g << 2) + (j0 & 3) * 1;
            const int a0i = i0 * 4 + ((j0 & 4) ? 2 : 0);
            const int i1 = (g << 2) + (j1 & 3);
            const int a1i = i1 * 4 + ((j1 & 4) ? 2 : 0);
#pragma unroll
            for (int tj = 0; tj < 8; tj++) {
                float p0 = __expf(s[st][tj][0] - mn0);
                float p1 = __expf(s[st][tj][1] - mn0);
                float p2 = __expf(s[st][tj][2] - mn1);
                float p3 = __expf(s[st][tj][3] - mn1);
                sm0 += p0 + p1; sm1 += p2 + p3;
                uint32_t* pb = &sP[w][st][tj << 7];
                pb[a0i + 0] = f2tf(p0);
                pb[a0i + 1] = f2tf(p2);
                pb[a1i + 0] = f2tf(p1);
                pb[a1i + 1] = f2tf(p3);
            }
            sm0 += __shfl_xor_sync(0xffffffffu, sm0, 1);
            sm0 += __shfl_xor_sync(0xffffffffu, sm0, 2);
            sm1 += __shfl_xor_sync(0xffffffffu, sm1, 1);
            sm1 += __shfl_xor_sync(0xffffffffu, sm1, 2);
            lrow[st][0] = lrow[st][0] * a0 + sm0;
            lrow[st][1] = lrow[st][1] * a1 + sm1;
#pragma unroll
            for (int nt = 0; nt < 8; nt++) {
                o[st][nt][0] *= a0; o[st][nt][1] *= a0;
                o[st][nt][2] *= a1; o[st][nt][3] *= a1;
            }
        }
        __syncwarp();

        // ---- O += P @ V ----
#pragma unroll
        for (int js2 = 0; js2 < 4; js2++) {
            uint4 p00 = *(const uint4*)&sP[w][0][((2 * js2)     * 32 + lane) * 4];
            uint4 p01 = *(const uint4*)&sP[w][0][((2 * js2 + 1) * 32 + lane) * 4];
            uint4 p10 = *(const uint4*)&sP[w][1][((2 * js2)     * 32 + lane) * 4];
            uint4 p11 = *(const uint4*)&sP[w][1][((2 * js2 + 1) * 32 + lane) * 4];
#pragma unroll
            for (int td = 0; td < 8; td++) {
                uint4 vf = VF4[((td << 6) + (kt << 2) + js2) * 32 + lane];
                mma8v(o[0][td], p00.x, p00.y, p00.z, p00.w, vf.x, vf.y);
                mma8v(o[0][td], p01.x, p01.y, p01.z, p01.w, vf.z, vf.w);
                mma8v(o[1][td], p10.x, p10.y, p10.z, p10.w, vf.x, vf.y);
                mma8v(o[1][td], p11.x, p11.y, p11.z, p11.w, vf.z, vf.w);
            }
        }
        __syncwarp();
    }

    // ---- epilogue: normalize, tf32-round, scatter to GEMM3's A-frag ----
    const int b_ = bh / NHEADS, h = bh % NHEADS;
#pragma unroll
    for (int st = 0; st < 2; st++) {
        const float inv0 = 1.f / lrow[st][0], inv1 = 1.f / lrow[st][1];
#pragma unroll
        for (int td = 0; td < 8; td++) {
#pragma unroll
            for (int e = 0; e < 4; e++) {
                int n = blockIdx.x * 128 + w * 32 + st * 16 + g + ((e >> 1) << 3);
                int m = (b_ << 10) + n;
                int col = (h << 6) + (td << 3) + (t << 1) + (e & 1);
                float val = o[st][td][e] * ((e & 2) ? inv1 : inv0);
                g_AOF[a_off(m, col, 96)] = f2tff(val);
            }
        }
    }
}

// ---------------------------------------------------------------------------
extern "C" void kernel_launch(void* const* d_in, const int* in_sizes, int n_in,
                              void* d_out, int out_size)
{
    (void)in_sizes; (void)n_in; (void)out_size;
    const float* x     = (const float*)d_in[0];
    const float* pos   = (const float*)d_in[1];
    const float* w_qkv = (const float*)d_in[2];
    const float* w_qkp = (const float*)d_in[3];
    const float* w_out = (const float*)d_in[4];
    const float* b_out = (const float*)d_in[5];
    float* out = (float*)d_out;

    void *pA_x, *pA_pos, *pB_qkv, *pB_qkp, *pB_out, *pAO;
    cudaGetSymbolAddress(&pA_x,   g_txA);
    cudaGetSymbolAddress(&pA_pos, g_tposA);
    cudaGetSymbolAddress(&pB_qkv, g_wqkvB);
    cudaGetSymbolAddress(&pB_qkp, g_wqkpB);
    cudaGetSymbolAddress(&pB_out, g_woutB);
    cudaGetSymbolAddress(&pAO,    g_AOF);

    // permutation pre-passes
    permA_k<<<3072, 256>>>(x,   (uint4*)pA_x,   768);
    permA_k<<<3072, 256>>>(pos, (uint4*)pA_pos, 768);
    permB_k<<<1728, 256>>>(w_qkv, (uint4*)pB_qkv, 768, 2304);
    permB_k<<<1152, 256>>>(w_qkp, (uint4*)pB_qkp, 768, 1536);
    permB_k<<< 576, 256>>>(w_out, (uint4*)pB_out, 768, 768);

    dim3 blk(128);
    // GEMM1: qkv -> QF/KF/VF fragment scatter
    gemm_frag<<<dim3(18, 32), blk>>>(
        (const uint4*)pA_x, (const uint4*)pB_qkv, nullptr, nullptr, 768, 2304, 0);
    // GEMM2: qk_pos -> QPF/KPF fragment scatter
    gemm_frag<<<dim3(12, 32), blk>>>(
        (const uint4*)pA_pos, (const uint4*)pB_qkp, nullptr, nullptr, 768, 1536, 1);
    // fused dual-score attention -> AOF (A-frag)
    attn_frag<<<dim3(8, 48), blk>>>();
    // GEMM3: out = ao @ w_out + b_out
    gemm_frag<<<dim3(6, 32), blk>>>(
        (const uint4*)pAO, (const uint4*)pB_out, b_out, out, 768, 768, 2);
}